// round 1
// baseline (speedup 1.0000x reference)
#include <cuda_runtime.h>
#include <cstdint>

#define C_INN 128
#define C_OUTT 64
#define BB 8
#define NN 2048
#define NEG_SLOPE 0.2f
#define LOG2E 1.4426950408889634f

// Scratch (static __device__ arrays: allocation-free per harness rules)
__device__ float g_Wh[BB * NN * C_OUTT];     // 4 MB
__device__ float g_f1[BB * NN];
__device__ float g_f2[BB * NN];
__device__ unsigned g_M[NN * (NN / 32)];     // 512 KB bitmask, [i][word]

// ---------------------------------------------------------------------------
// Kernel A1: Wh = x @ W ; f1 = Wh@a1 ; f2 = Wh@a2
// One warp per (b,n) row. W staged in shared (32KB), x row staged in shared.
// ---------------------------------------------------------------------------
__global__ void __launch_bounds__(256) k_wh(const float* __restrict__ x,
                                            const float* __restrict__ W,
                                            const float* __restrict__ attn)
{
    __shared__ float Wsh[C_INN * C_OUTT];
    __shared__ float xsh[8][C_INN];

    int t = threadIdx.x;
    for (int k = t; k < C_INN * C_OUTT; k += 256) Wsh[k] = W[k];

    int warp = t >> 5, lane = t & 31;
    int row = blockIdx.x * 8 + warp;

    // stage x row (128 floats) — 4 per lane, coalesced float4
    const float4* xr = (const float4*)(x + (size_t)row * C_INN);
    ((float4*)xsh[warp])[lane] = xr[lane];
    __syncthreads();

    float acc0 = 0.f, acc1 = 0.f;
    #pragma unroll 8
    for (int c = 0; c < C_INN; c++) {
        float xc = xsh[warp][c];                       // broadcast
        acc0 = fmaf(xc, Wsh[c * C_OUTT + lane],      acc0);
        acc1 = fmaf(xc, Wsh[c * C_OUTT + 32 + lane], acc1);
    }

    g_Wh[(size_t)row * C_OUTT + lane]      = acc0;
    g_Wh[(size_t)row * C_OUTT + 32 + lane] = acc1;

    float p1 = acc0 * attn[lane] + acc1 * attn[32 + lane];
    float p2 = acc0 * attn[64 + lane] + acc1 * attn[96 + lane];
    #pragma unroll
    for (int s = 16; s; s >>= 1) {
        p1 += __shfl_xor_sync(0xffffffffu, p1, s);
        p2 += __shfl_xor_sync(0xffffffffu, p2, s);
    }
    if (lane == 0) { g_f1[row] = p1; g_f2[row] = p2; }
}

// ---------------------------------------------------------------------------
// Kernel A2: bit-pack mask (A > 0). One thread per 32-bit word (reads 128B).
// ---------------------------------------------------------------------------
__global__ void __launch_bounds__(256) k_mask(const int* __restrict__ A)
{
    int idx = blockIdx.x * 256 + threadIdx.x;          // word index, N*N/32 total
    const int* p = A + (size_t)idx * 32;
    unsigned m = 0;
    #pragma unroll
    for (int k = 0; k < 32; k++)
        if (p[k] > 0) m |= (1u << k);
    g_M[idx] = m;
}

// ---------------------------------------------------------------------------
// Kernel B: masked-softmax aggregation, fp32x2 packed FMA.
// Grid: 8 batches x 16 i-tiles of 128. CTA = 256 threads:
//   thread = (i_local in [0,128), half in {0,1}); each thread owns 32 output
//   channels of one i-row (16 x f32x2 accumulators).
// Wh j-tile (128 x 64 f32 = 32KB) staged in SMEM, broadcast-read per j.
// ---------------------------------------------------------------------------
__device__ __forceinline__ unsigned long long ffma2(unsigned long long a,
                                                    unsigned long long b,
                                                    unsigned long long c)
{
    unsigned long long d;
    asm("fma.rn.f32x2 %0, %1, %2, %3;" : "=l"(d) : "l"(a), "l"(b), "l"(c));
    return d;
}

__global__ void __launch_bounds__(256) k_gat(float* __restrict__ out)
{
    __shared__ float Whs[128 * C_OUTT];   // 32 KB
    __shared__ float f2s[128];

    int t = threadIdx.x;
    int il = t & 127, half = t >> 7;
    int b = blockIdx.x >> 4, tile = blockIdx.x & 15;
    int i = tile * 128 + il;
    int row = b * NN + i;

    float f1i = g_f1[row];

    unsigned long long acc[16];
    #pragma unroll
    for (int k = 0; k < 16; k++) acc[k] = 0ull;
    float Z = 0.f;

    const float*    Whb  = g_Wh + (size_t)b * NN * C_OUTT;
    const float*    f2b  = g_f2 + (size_t)b * NN;
    const unsigned* Mrow = g_M  + (size_t)i * (NN / 32);

    unsigned sbase = (unsigned)__cvta_generic_to_shared(Whs) + half * 128; // +32ch*4B

    for (int jt = 0; jt < 16; jt++) {
        __syncthreads();
        // stage Wh tile: 2048 float4 across 256 threads (8 each), coalesced
        const float4* src = (const float4*)(Whb + (size_t)jt * 128 * C_OUTT);
        float4* dst = (float4*)Whs;
        #pragma unroll
        for (int k = 0; k < 8; k++) dst[t + k * 256] = src[t + k * 256];
        if (t < 128) f2s[t] = f2b[jt * 128 + t];
        __syncthreads();

        #pragma unroll
        for (int jw = 0; jw < 4; jw++) {
            unsigned mw = Mrow[jt * 4 + jw];
            #pragma unroll 8
            for (int jj = 0; jj < 32; jj++) {
                int j = jw * 32 + jj;
                float e = f1i + f2s[j];
                e = (e >= 0.f) ? e : NEG_SLOPE * e;
                float w;
                asm("ex2.approx.f32 %0, %1;" : "=f"(w) : "f"(e * LOG2E));
                w = ((mw >> jj) & 1u) ? w : 0.f;
                Z += w;
                unsigned long long w2;
                asm("mov.b64 %0, {%1, %1};" : "=l"(w2) : "f"(w));
                unsigned saddr = sbase + (unsigned)j * (C_OUTT * 4);
                #pragma unroll
                for (int k = 0; k < 8; k++) {
                    unsigned long long va, vb;
                    asm("ld.shared.v2.u64 {%0, %1}, [%2];"
                        : "=l"(va), "=l"(vb) : "r"(saddr + k * 16));
                    acc[2 * k]     = ffma2(w2, va, acc[2 * k]);
                    acc[2 * k + 1] = ffma2(w2, vb, acc[2 * k + 1]);
                }
            }
        }
    }

    float inv = 1.f / Z;
    float* op = out + (size_t)row * C_OUTT + half * 32;
    #pragma unroll
    for (int k = 0; k < 16; k++) {
        float lo, hi;
        asm("mov.b64 {%0, %1}, %2;" : "=f"(lo), "=f"(hi) : "l"(acc[k]));
        op[2 * k]     = lo * inv;
        op[2 * k + 1] = hi * inv;
    }
}

// ---------------------------------------------------------------------------
extern "C" void kernel_launch(void* const* d_in, const int* in_sizes, int n_in,
                              void* d_out, int out_size)
{
    const float* x    = (const float*)d_in[0];   // (8,2048,128) f32
    const int*   A    = (const int*)d_in[1];     // (2048,2048) i32
    const float* W    = (const float*)d_in[2];   // (128,64) f32
    const float* attn = (const float*)d_in[3];   // (128,1) f32
    float* out = (float*)d_out;                  // (8,2048,64) f32

    k_wh  <<<BB * NN / 8, 256>>>(x, W, attn);
    k_mask<<<(NN * (NN / 32)) / 256, 256>>>(A);
    k_gat <<<BB * (NN / 128), 256>>>(out);
}

// round 3
// speedup vs baseline: 3.4539x; 3.4539x over previous
#include <cuda_runtime.h>
#include <cstdint>

#define C_INN 128
#define C_OUTT 64
#define BB 8
#define NN 2048
#define LOG2E 1.4426950408889634f

// ---------------------------------------------------------------------------
// Scratch (__device__ globals: allocation-free per harness rules)
// ---------------------------------------------------------------------------
__device__ float  g_Wh[BB * NN * C_OUTT];       // tf32-rounded Wh, 4 MB
__device__ float2 g_E1i[BB * NN];               // {exp(f1), exp(0.2 f1)}
__device__ float2 g_E2i[BB * NN];               // {exp(f2), exp(0.2 f2)}
__device__ unsigned g_Mt[(NN / 32) * NN];       // transposed bitmask [word][i]

__device__ __forceinline__ float fast_exp(float x) {
    float r;
    asm("ex2.approx.f32 %0, %1;" : "=f"(r) : "f"(x * LOG2E));
    return r;
}

__device__ __forceinline__ uint32_t cvt_tf32(float f) {
    uint32_t u;
    asm("cvt.rna.tf32.f32 %0, %1;" : "=r"(u) : "f"(f));
    return u;
}

// ---------------------------------------------------------------------------
// Kernel 1: Wh = x @ W (register-blocked, 8 rows/warp); fused f1/f2 + exp.
// Wh stored tf32-rounded (only consumed as tf32 MMA operand).
// ---------------------------------------------------------------------------
__global__ void __launch_bounds__(256) k_wh(const float* __restrict__ x,
                                            const float* __restrict__ W,
                                            const float* __restrict__ attn)
{
    __shared__ float Wsh[C_INN * C_OUTT];   // 32 KB

    int t = threadIdx.x, warp = t >> 5, lane = t & 31;
    int base_row = blockIdx.x * 64 + warp * 8;

    for (int k = t; k < C_INN * C_OUTT; k += 256) Wsh[k] = W[k];
    __syncthreads();

    float a0[8], a1[8];
    #pragma unroll
    for (int q = 0; q < 8; q++) { a0[q] = 0.f; a1[q] = 0.f; }

    for (int c4 = 0; c4 < C_INN; c4 += 4) {
        float wA[4], wB[4];
        #pragma unroll
        for (int cc = 0; cc < 4; cc++) {
            wA[cc] = Wsh[(c4 + cc) * C_OUTT + lane];
            wB[cc] = Wsh[(c4 + cc) * C_OUTT + 32 + lane];
        }
        #pragma unroll
        for (int q = 0; q < 8; q++) {
            float4 xv = *(const float4*)(x + (size_t)(base_row + q) * C_INN + c4);
            a0[q] = fmaf(xv.x, wA[0], a0[q]); a1[q] = fmaf(xv.x, wB[0], a1[q]);
            a0[q] = fmaf(xv.y, wA[1], a0[q]); a1[q] = fmaf(xv.y, wB[1], a1[q]);
            a0[q] = fmaf(xv.z, wA[2], a0[q]); a1[q] = fmaf(xv.z, wB[2], a1[q]);
            a0[q] = fmaf(xv.w, wA[3], a0[q]); a1[q] = fmaf(xv.w, wB[3], a1[q]);
        }
    }

    float at1a = attn[lane], at1b = attn[32 + lane];
    float at2a = attn[64 + lane], at2b = attn[96 + lane];

    #pragma unroll
    for (int q = 0; q < 8; q++) {
        int row = base_row + q;
        float p1 = a0[q] * at1a + a1[q] * at1b;
        float p2 = a0[q] * at2a + a1[q] * at2b;
        #pragma unroll
        for (int s = 16; s; s >>= 1) {
            p1 += __shfl_xor_sync(0xffffffffu, p1, s);
            p2 += __shfl_xor_sync(0xffffffffu, p2, s);
        }
        if (lane == 0) {
            g_E1i[row] = make_float2(fast_exp(p1), fast_exp(0.2f * p1));
            g_E2i[row] = make_float2(fast_exp(p2), fast_exp(0.2f * p2));
        }
        g_Wh[(size_t)row * C_OUTT + lane]      = __uint_as_float(cvt_tf32(a0[q]));
        g_Wh[(size_t)row * C_OUTT + 32 + lane] = __uint_as_float(cvt_tf32(a1[q]));
    }
}

// ---------------------------------------------------------------------------
// Kernel 2: bit-pack mask, stored TRANSPOSED: g_Mt[word][i].
// Block = 1024 consecutive elements of one row of A.
// ---------------------------------------------------------------------------
__global__ void __launch_bounds__(256) k_mask(const int* __restrict__ A)
{
    __shared__ unsigned char nib[256];
    int t = threadIdx.x;
    int i = blockIdx.x >> 1;                 // A row
    int wb = (blockIdx.x & 1) * 32;          // word base within row
    int4 v = ((const int4*)A)[(size_t)blockIdx.x * 256 + t];
    unsigned n = (v.x > 0 ? 1u : 0u) | (v.y > 0 ? 2u : 0u) |
                 (v.z > 0 ? 4u : 0u) | (v.w > 0 ? 8u : 0u);
    nib[t] = (unsigned char)n;
    __syncthreads();
    if (t < 32) {
        const unsigned char* p = nib + t * 8;
        unsigned w = 0;
        #pragma unroll
        for (int s = 0; s < 8; s++) w |= ((unsigned)(p[s] & 0xFu)) << (4 * s);
        g_Mt[(size_t)(wb + t) * NN + i] = w;
    }
}

// ---------------------------------------------------------------------------
// Kernel 3: fused P-build + mma.sync tf32 aggregation.
// CTA = 512 threads = 16 warps in an 8(M) x 2(N) grid. One (batch, 128-row
// i-tile) per CTA; 16 j-tiles of 128. Warp tile: M=16, N=32.
// P fragments built in registers (no SMEM): w = mask * max(E1*E2, E1p*E2p).
// Wh tile staged in SMEM (stride 72 -> conflict-free B-fragment loads),
// register double-buffered across j-tiles.
// ---------------------------------------------------------------------------
__global__ void __launch_bounds__(512, 1) k_gat(float* __restrict__ out)
{
    __shared__ float    Whs[128 * 72];   // 36 KB
    __shared__ float2   E2s[128];
    __shared__ unsigned Msh[4][128];
    __shared__ float    zsh[128];

    int t = threadIdx.x;
    int lane = t & 31, w = t >> 5;
    int warpM = w >> 1, nwarp = w & 1;
    int g = lane >> 2, tk = lane & 3;
    int b = blockIdx.x >> 4, i0 = (blockIdx.x & 15) << 7;
    int b2048 = b * NN;

    int r0 = warpM * 16 + g, r1 = r0 + 8;          // local rows
    float2 e1a = g_E1i[b2048 + i0 + r0];
    float2 e1b = g_E1i[b2048 + i0 + r1];

    float c[4][4];
    #pragma unroll
    for (int nt = 0; nt < 4; nt++)
        #pragma unroll
        for (int k = 0; k < 4; k++) c[nt][k] = 0.f;
    float z0 = 0.f, z1 = 0.f;

    unsigned mt0 = 1u << tk;     // bit masks for k0 / k1 within a byte-lane
    unsigned mt1 = 16u << tk;

    const float4* wh4 = (const float4*)(g_Wh + (size_t)b2048 * C_OUTT);

    // register prefetch buffers
    float4 pw[4]; unsigned pm; float2 pe;
    {
        #pragma unroll
        for (int k = 0; k < 4; k++) pw[k] = wh4[t + k * 512];
        pm = g_Mt[(size_t)(t >> 7) * NN + i0 + (t & 127)];
        if (t < 128) pe = g_E2i[b2048 + t];
    }

    for (int jt = 0; jt < 16; jt++) {
        __syncthreads();                       // previous compute done
        // stage prefetched tile
        #pragma unroll
        for (int k = 0; k < 4; k++) {
            int idx = t + k * 512;
            *(float4*)&Whs[(idx >> 4) * 72 + ((idx & 15) << 2)] = pw[k];
        }
        Msh[t >> 7][t & 127] = pm;
        if (t < 128) E2s[t] = pe;
        __syncthreads();

        // prefetch next tile (wraps at 15 -> harmless re-read of tile 0)
        {
            int jn = (jt + 1) & 15;
            #pragma unroll
            for (int k = 0; k < 4; k++) pw[k] = wh4[jn * 2048 + t + k * 512];
            pm = g_Mt[(size_t)(jn * 4 + (t >> 7)) * NN + i0 + (t & 127)];
            if (t < 128) pe = g_E2i[b2048 + jn * 128 + t];
        }

        // compute this j-tile: 16 k-steps of 8 j's
        unsigned mw0 = 0, mw1 = 0;
        #pragma unroll
        for (int ks = 0; ks < 16; ks++) {
            if ((ks & 3) == 0) {
                mw0 = Msh[ks >> 2][r0];
                mw1 = Msh[ks >> 2][r1];
            }
            int j0 = ks * 8;
            float2 ea = E2s[j0 + tk];
            float2 eb = E2s[j0 + tk + 4];
            unsigned s0 = mt0 << ((ks & 3) * 8);
            unsigned s1 = mt1 << ((ks & 3) * 8);

            float m;
            m = fmaxf(e1a.x * ea.x, e1a.y * ea.y);
            float a0 = (mw0 & s0) ? m : 0.f;
            m = fmaxf(e1b.x * ea.x, e1b.y * ea.y);
            float a1 = (mw1 & s0) ? m : 0.f;
            m = fmaxf(e1a.x * eb.x, e1a.y * eb.y);
            float a2 = (mw0 & s1) ? m : 0.f;
            m = fmaxf(e1b.x * eb.x, e1b.y * eb.y);
            float a3 = (mw1 & s1) ? m : 0.f;

            z0 += a0 + a2;
            z1 += a1 + a3;

            uint32_t ua0 = __float_as_uint(a0), ua1 = __float_as_uint(a1);
            uint32_t ua2 = __float_as_uint(a2), ua3 = __float_as_uint(a3);

            int bbase = (j0 + tk) * 72 + nwarp * 32 + g;
            #pragma unroll
            for (int nt = 0; nt < 4; nt++) {
                uint32_t ub0 = __float_as_uint(Whs[bbase + nt * 8]);
                uint32_t ub1 = __float_as_uint(Whs[bbase + 288 + nt * 8]);
                asm volatile(
                    "mma.sync.aligned.m16n8k8.row.col.f32.tf32.tf32.f32 "
                    "{%0,%1,%2,%3}, {%4,%5,%6,%7}, {%8,%9}, {%0,%1,%2,%3};"
                    : "+f"(c[nt][0]), "+f"(c[nt][1]), "+f"(c[nt][2]), "+f"(c[nt][3])
                    : "r"(ua0), "r"(ua1), "r"(ua2), "r"(ua3), "r"(ub0), "r"(ub1));
            }
        }
    }

    // per-row Z: reduce over the 4 lanes of each row group (n-warp 0 writes)
    z0 += __shfl_xor_sync(0xffffffffu, z0, 1);
    z0 += __shfl_xor_sync(0xffffffffu, z0, 2);
    z1 += __shfl_xor_sync(0xffffffffu, z1, 1);
    z1 += __shfl_xor_sync(0xffffffffu, z1, 2);
    if (nwarp == 0 && tk == 0) { zsh[r0] = z0; zsh[r1] = z1; }
    __syncthreads();

    float inv0 = 1.f / zsh[r0];
    float inv1 = 1.f / zsh[r1];

    float* o0 = out + (size_t)(b2048 + i0 + r0) * C_OUTT + nwarp * 32 + tk * 2;
    float* o1 = out + (size_t)(b2048 + i0 + r1) * C_OUTT + nwarp * 32 + tk * 2;
    #pragma unroll
    for (int nt = 0; nt < 4; nt++) {
        *(float2*)(o0 + nt * 8) = make_float2(c[nt][0] * inv0, c[nt][1] * inv0);
        *(float2*)(o1 + nt * 8) = make_float2(c[nt][2] * inv1, c[nt][3] * inv1);
    }
}

// ---------------------------------------------------------------------------
extern "C" void kernel_launch(void* const* d_in, const int* in_sizes, int n_in,
                              void* d_out, int out_size)
{
    const float* x    = (const float*)d_in[0];   // (8,2048,128) f32
    const int*   A    = (const int*)d_in[1];     // (2048,2048) i32
    const float* W    = (const float*)d_in[2];   // (128,64) f32
    const float* attn = (const float*)d_in[3];   // (128,1) f32
    float* out = (float*)d_out;                  // (8,2048,64) f32

    k_wh  <<<BB * NN / 64, 256>>>(x, W, attn);
    k_mask<<<NN * NN / 1024, 256>>>(A);
    k_gat <<<BB * (NN / 128), 512>>>(out);
}